// round 2
// baseline (speedup 1.0000x reference)
#include <cuda_runtime.h>

// ---------------------------------------------------------------------------
// Fused MLP, packed-f32x2 version:
//   a1 = lrelu(a @ Wa + ba)        [B,45] -> [B,68]
//   b1 = lrelu(b @ Wb + bb)        [B,102] -> [B,68]
//   c  = concat(a1, b1, meta)      [B,140]
//   10 x (c = lrelu(c @ Wi + Bi))  140->34->34->20->20->20->20->20->5->2->1
//
// One thread per row. All weights staged in SMEM, N-padded to a multiple of 4
// and zero-filled (pad bias 0, lrelu(0)=0 -> pads stay exactly 0). All inner
// products use fma.rn.f32x2 (2 MACs / issue slot). Weight reads are
// warp-broadcast LDS.128 (conflict-free). Layer-0 accumulation is split so
// the 140-wide concat never exists as a live register array.
// ---------------------------------------------------------------------------

#define NTHREADS 256

using ull = unsigned long long;

// SMEM layout (float offsets; every offset multiple of 4 -> 16B aligned rows)
constexpr int OF_Wa = 0;                 // 45*68  = 3060
constexpr int OF_ba = OF_Wa + 3060;      // 68
constexpr int OF_Wb = OF_ba + 68;        // 102*68 = 6936
constexpr int OF_bb = OF_Wb + 6936;      // 68
constexpr int OF_W0 = OF_bb + 68;        // 140*36 = 5040
constexpr int OF_B0 = OF_W0 + 5040;      // 36
constexpr int OF_W1 = OF_B0 + 36;        // 34*36  = 1224
constexpr int OF_B1 = OF_W1 + 1224;      // 36
constexpr int OF_W2 = OF_B1 + 36;        // 34*20  = 680
constexpr int OF_B2 = OF_W2 + 680;       // 20
constexpr int OF_W3 = OF_B2 + 20;        // 20*20  = 400
constexpr int OF_B3 = OF_W3 + 400;       // 20
constexpr int OF_W4 = OF_B3 + 20;        // 400
constexpr int OF_B4 = OF_W4 + 400;       // 20
constexpr int OF_W5 = OF_B4 + 20;        // 400
constexpr int OF_B5 = OF_W5 + 400;       // 20
constexpr int OF_W6 = OF_B5 + 20;        // 400
constexpr int OF_B6 = OF_W6 + 400;       // 20
constexpr int OF_W7 = OF_B6 + 20;        // 20*8 = 160
constexpr int OF_B7 = OF_W7 + 160;       // 8
constexpr int OF_W8 = OF_B7 + 8;         // 5*4 = 20
constexpr int OF_B8 = OF_W8 + 20;        // 4
constexpr int OF_W9 = OF_B8 + 4;         // 2*4 = 8
constexpr int OF_B9 = OF_W9 + 8;         // 4
constexpr int SMEM_FLOATS = OF_B9 + 4;   // 19052
constexpr int SMEM_BYTES  = SMEM_FLOATS * 4;  // 76208 bytes

struct Params {
    const float* p[27];
};

// ---- packed f32x2 helpers ----
__device__ __forceinline__ ull pack2(float x) {
    ull r;
    asm("mov.b64 %0, {%1, %1};" : "=l"(r) : "f"(x));
    return r;
}
__device__ __forceinline__ void unpack2(ull v, float& lo, float& hi) {
    asm("mov.b64 {%0, %1}, %2;" : "=f"(lo), "=f"(hi) : "l"(v));
}
__device__ __forceinline__ ull fma2(ull a, ull b, ull c) {
    ull d;
    asm("fma.rn.f32x2 %0, %1, %2, %3;" : "=l"(d) : "l"(a), "l"(b), "l"(c));
    return d;
}

__device__ __forceinline__ float lrelu1(float x) {
    return x > 0.0f ? x : 0.01f * x;
}

// ---- cooperative weight staging (padded, zero-filled) ----
__device__ __forceinline__ void load_mat(float* __restrict__ dst,
                                         const float* __restrict__ src,
                                         int din, int dout, int dpad) {
    for (int i = threadIdx.x; i < din * dpad; i += NTHREADS) {
        int r = i / dpad;
        int c = i - r * dpad;
        dst[i] = (c < dout) ? src[r * dout + c] : 0.0f;
    }
}
__device__ __forceinline__ void load_vec(float* __restrict__ dst,
                                         const float* __restrict__ src,
                                         int n, int npad) {
    for (int i = threadIdx.x; i < npad; i += NTHREADS) {
        dst[i] = (i < n) ? src[i] : 0.0f;
    }
}

// acc (NP/2 packed) += x[k] * W[k][:]   W in SMEM, row length NP (mult of 4).
// Each 16B LDS feeds 2 FFMA2 (4 MACs); loads are full-warp broadcasts.
template <int K, int NP>
__device__ __forceinline__ void gemv2(const float* __restrict__ x,
                                      const float* __restrict__ w,
                                      ull* __restrict__ acc) {
#pragma unroll
    for (int k = 0; k < K; ++k) {
        const ull xv = pack2(x[k]);
        const ull* wr = reinterpret_cast<const ull*>(w + k * NP);
#pragma unroll
        for (int j = 0; j < NP / 2; j += 2) {
            const ulonglong2 wv = *reinterpret_cast<const ulonglong2*>(wr + j);
            acc[j + 0] = fma2(xv, wv.x, acc[j + 0]);
            acc[j + 1] = fma2(xv, wv.y, acc[j + 1]);
        }
    }
}

// acc init from packed bias in SMEM (8B aligned; base offsets are 16B aligned)
template <int NP>
__device__ __forceinline__ void init_bias2(ull* __restrict__ acc,
                                           const float* __restrict__ b) {
    const ull* bp = reinterpret_cast<const ull*>(b);
#pragma unroll
    for (int j = 0; j < NP / 2; ++j) acc[j] = bp[j];
}

// unpack packed accumulator -> float array with leaky-relu applied
template <int NP>
__device__ __forceinline__ void act_unpack(const ull* __restrict__ acc,
                                           float* __restrict__ h) {
#pragma unroll
    for (int j = 0; j < NP / 2; ++j) {
        float lo, hi;
        unpack2(acc[j], lo, hi);
        h[2 * j + 0] = lrelu1(lo);
        h[2 * j + 1] = lrelu1(hi);
    }
}

__global__ __launch_bounds__(NTHREADS, 1)
void mlp_fused_kernel(Params prm, float* __restrict__ out, int nrows) {
    extern __shared__ float sw[];

    // ---- stage all weights into SMEM (padded) ----
    load_mat(sw + OF_Wa, prm.p[3], 45, 68, 68);
    load_vec(sw + OF_ba, prm.p[4], 68, 68);
    load_mat(sw + OF_Wb, prm.p[5], 102, 68, 68);
    load_vec(sw + OF_bb, prm.p[6], 68, 68);
    load_mat(sw + OF_W0, prm.p[7], 140, 34, 36);
    load_vec(sw + OF_B0, prm.p[8], 34, 36);
    load_mat(sw + OF_W1, prm.p[9], 34, 34, 36);
    load_vec(sw + OF_B1, prm.p[10], 34, 36);
    load_mat(sw + OF_W2, prm.p[11], 34, 20, 20);
    load_vec(sw + OF_B2, prm.p[12], 20, 20);
    load_mat(sw + OF_W3, prm.p[13], 20, 20, 20);
    load_vec(sw + OF_B3, prm.p[14], 20, 20);
    load_mat(sw + OF_W4, prm.p[15], 20, 20, 20);
    load_vec(sw + OF_B4, prm.p[16], 20, 20);
    load_mat(sw + OF_W5, prm.p[17], 20, 20, 20);
    load_vec(sw + OF_B5, prm.p[18], 20, 20);
    load_mat(sw + OF_W6, prm.p[19], 20, 20, 20);
    load_vec(sw + OF_B6, prm.p[20], 20, 20);
    load_mat(sw + OF_W7, prm.p[21], 20, 5, 8);
    load_vec(sw + OF_B7, prm.p[22], 5, 8);
    load_mat(sw + OF_W8, prm.p[23], 5, 2, 4);
    load_vec(sw + OF_B8, prm.p[24], 2, 4);
    load_mat(sw + OF_W9, prm.p[25], 2, 1, 4);
    load_vec(sw + OF_B9, prm.p[26], 1, 4);
    __syncthreads();

    const int row = blockIdx.x * NTHREADS + threadIdx.x;
    if (row >= nrows) return;

    const float* __restrict__ A  = prm.p[0] + (long)row * 45;
    const float* __restrict__ Bi = prm.p[1] + (long)row * 102;
    const float* __restrict__ Mt = prm.p[2] + (long)row * 4;

    // ---- tower A: a1 = lrelu(a @ Wa + ba), K chunked 15+15+15 ----
    ull tacc[34];
    init_bias2<68>(tacc, sw + OF_ba);
    {
        float xa[15];
#pragma unroll
        for (int c = 0; c < 3; ++c) {
#pragma unroll
            for (int k = 0; k < 15; ++k) xa[k] = A[c * 15 + k];
            gemv2<15, 68>(xa, sw + OF_Wa + c * 15 * 68, tacc);
        }
    }
    float t1[68];
    act_unpack<68>(tacc, t1);

    // layer-0 accumulator; fold in a1's contribution now so t1/tacc regs are
    // reusable for the b tower (the 140-wide concat never materializes).
    ull h0acc[18];
    init_bias2<36>(h0acc, sw + OF_B0);
    gemv2<68, 36>(t1, sw + OF_W0, h0acc);            // rows 0..67 of W0

    // ---- tower B: b1 = lrelu(b @ Wb + bb), K chunked 3 x 34 ----
    init_bias2<68>(tacc, sw + OF_bb);
    {
        float xb[34];
#pragma unroll
        for (int c = 0; c < 3; ++c) {
#pragma unroll
            for (int k = 0; k < 34; ++k) xb[k] = Bi[c * 34 + k];
            gemv2<34, 68>(xb, sw + OF_Wb + c * 34 * 68, tacc);
        }
    }
    act_unpack<68>(tacc, t1);
    gemv2<68, 36>(t1, sw + OF_W0 + 68 * 36, h0acc);  // rows 68..135 of W0

    // ---- meta contribution to layer 0 ----
    {
        float xm[4];
#pragma unroll
        for (int k = 0; k < 4; ++k) xm[k] = Mt[k];
        gemv2<4, 36>(xm, sw + OF_W0 + 136 * 36, h0acc);  // rows 136..139
    }
    float h0[36];
    act_unpack<36>(h0acc, h0);   // pads stay exactly 0

    // ---- layer 1: 34 -> 34 (pad 36) ----
    ull acc36[18];
    init_bias2<36>(acc36, sw + OF_B1);
    gemv2<34, 36>(h0, sw + OF_W1, acc36);
    float h1[36];
    act_unpack<36>(acc36, h1);

    // ---- layer 2: 34 -> 20 ----
    ull acc20[10];
    init_bias2<20>(acc20, sw + OF_B2);
    gemv2<34, 20>(h1, sw + OF_W2, acc20);
    float h2[20];
    act_unpack<20>(acc20, h2);

    // ---- layers 3..6: 20 -> 20 ----
    float h3[20];
    init_bias2<20>(acc20, sw + OF_B3);
    gemv2<20, 20>(h2, sw + OF_W3, acc20);
    act_unpack<20>(acc20, h3);

    init_bias2<20>(acc20, sw + OF_B4);
    gemv2<20, 20>(h3, sw + OF_W4, acc20);
    act_unpack<20>(acc20, h2);

    init_bias2<20>(acc20, sw + OF_B5);
    gemv2<20, 20>(h2, sw + OF_W5, acc20);
    act_unpack<20>(acc20, h3);

    init_bias2<20>(acc20, sw + OF_B6);
    gemv2<20, 20>(h3, sw + OF_W6, acc20);
    act_unpack<20>(acc20, h2);

    // ---- layer 7: 20 -> 5 (pad 8) ----
    ull acc8[4];
    init_bias2<8>(acc8, sw + OF_B7);
    gemv2<20, 8>(h2, sw + OF_W7, acc8);
    float h7[8];
    act_unpack<8>(acc8, h7);

    // ---- layer 8: 5 -> 2 (pad 4) ----
    ull acc4[2];
    init_bias2<4>(acc4, sw + OF_B8);
    gemv2<5, 4>(h7, sw + OF_W8, acc4);
    float h8[4];
    act_unpack<4>(acc4, h8);

    // ---- layer 9: 2 -> 1 (pad 4) ----
    init_bias2<4>(acc4, sw + OF_B9);
    gemv2<2, 4>(h8, sw + OF_W9, acc4);
    float lo, hi;
    unpack2(acc4[0], lo, hi);
    out[row] = lrelu1(lo);
}

extern "C" void kernel_launch(void* const* d_in, const int* in_sizes, int n_in,
                              void* d_out, int out_size) {
    Params prm;
    for (int i = 0; i < 27; ++i) prm.p[i] = (const float*)d_in[i];
    const int nrows = in_sizes[0] / 45;

    cudaFuncSetAttribute(mlp_fused_kernel,
                         cudaFuncAttributeMaxDynamicSharedMemorySize,
                         SMEM_BYTES);

    const int grid = (nrows + NTHREADS - 1) / NTHREADS;
    mlp_fused_kernel<<<grid, NTHREADS, SMEM_BYTES>>>(prm, (float*)d_out, nrows);
}

// round 4
// speedup vs baseline: 1.1516x; 1.1516x over previous
#include <cuda_runtime.h>

// ---------------------------------------------------------------------------
// Fused MLP, packed-f32x2 + fused activation-consume version.
//   a1 = lrelu(a @ Wa + ba)        [B,45] -> [B,68]
//   b1 = lrelu(b @ Wb + bb)        [B,102] -> [B,68]
//   c  = concat(a1, b1, meta)      [B,140]
//   10 x (c = lrelu(c @ Wi + Bi))  140->34->34->20->20->20->20->20->5->2->1
//
// One thread per row, 512 threads/block (__launch_bounds__ caps regs at 128
// -> 16 warps/SM). No intermediate activation array is ever materialized:
// each finished packed accumulator pair is unpacked, lrelu'd, and immediately
// folded into the next layer's accumulator (2 weight rows per pair), so its
// registers die on the spot. Weights live in SMEM, N-padded to mult-of-4 and
// K-padded to mult-of-2 where needed, zero-filled (pad activations stay
// exactly 0 through lrelu). All MACs are fma.rn.f32x2.
// ---------------------------------------------------------------------------

#define NTHREADS 512

using ull = unsigned long long;

// SMEM layout (float offsets; all multiples of 4 -> 16B-aligned rows)
constexpr int OF_Wa = 0;                 // 45*68  = 3060
constexpr int OF_ba = OF_Wa + 3060;      // 68
constexpr int OF_Wb = OF_ba + 68;        // 102*68 = 6936
constexpr int OF_bb = OF_Wb + 6936;      // 68
constexpr int OF_W0 = OF_bb + 68;        // 140*36 = 5040
constexpr int OF_B0 = OF_W0 + 5040;      // 36
constexpr int OF_W1 = OF_B0 + 36;        // 34*36  = 1224
constexpr int OF_B1 = OF_W1 + 1224;      // 36
constexpr int OF_W2 = OF_B1 + 36;        // 34*20  = 680
constexpr int OF_B2 = OF_W2 + 680;       // 20
constexpr int OF_W3 = OF_B2 + 20;        // 20*20  = 400
constexpr int OF_B3 = OF_W3 + 400;       // 20
constexpr int OF_W4 = OF_B3 + 20;        // 400
constexpr int OF_B4 = OF_W4 + 400;       // 20
constexpr int OF_W5 = OF_B4 + 20;        // 400
constexpr int OF_B5 = OF_W5 + 400;       // 20
constexpr int OF_W6 = OF_B5 + 20;        // 400
constexpr int OF_B6 = OF_W6 + 400;       // 20
constexpr int OF_W7 = OF_B6 + 20;        // 20*8 = 160
constexpr int OF_B7 = OF_W7 + 160;       // 8
constexpr int OF_W8 = OF_B7 + 8;         // 8*4 = 32 (K padded 5->8)
constexpr int OF_B8 = OF_W8 + 32;        // 4
constexpr int OF_W9 = OF_B8 + 4;         // 4*4 = 16 (K padded 2->4)
constexpr int OF_B9 = OF_W9 + 16;        // 4
constexpr int SMEM_FLOATS = OF_B9 + 4;   // 19076
constexpr int SMEM_BYTES  = SMEM_FLOATS * 4;

struct Params {
    const float* p[27];
};

// ---- packed f32x2 helpers ----
__device__ __forceinline__ ull pack2(float x) {
    ull r;
    asm("mov.b64 %0, {%1, %1};" : "=l"(r) : "f"(x));
    return r;
}
__device__ __forceinline__ void unpack2(ull v, float& lo, float& hi) {
    asm("mov.b64 {%0, %1}, %2;" : "=f"(lo), "=f"(hi) : "l"(v));
}
__device__ __forceinline__ ull fma2(ull a, ull b, ull c) {
    ull d;
    asm("fma.rn.f32x2 %0, %1, %2, %3;" : "=l"(d) : "l"(a), "l"(b), "l"(c));
    return d;
}
__device__ __forceinline__ float lrelu1(float x) {
    return x > 0.0f ? x : 0.01f * x;
}

// ---- cooperative weight staging (N-padded + K-padded, zero-filled) ----
__device__ __forceinline__ void load_mat(float* __restrict__ dst,
                                         const float* __restrict__ src,
                                         int din, int dout, int dpad, int kpad) {
    for (int i = threadIdx.x; i < kpad * dpad; i += NTHREADS) {
        int r = i / dpad;
        int c = i - r * dpad;
        dst[i] = (r < din && c < dout) ? src[r * dout + c] : 0.0f;
    }
}
__device__ __forceinline__ void load_vec(float* __restrict__ dst,
                                         const float* __restrict__ src,
                                         int n, int npad) {
    for (int i = threadIdx.x; i < npad; i += NTHREADS) {
        dst[i] = (i < n) ? src[i] : 0.0f;
    }
}

// acc[NP/2 packed] += xv(bcast pair) * Wrow ; one LDS.128 feeds 2 FFMA2.
template <int NP>
__device__ __forceinline__ void rowfma(ull xv, const float* __restrict__ w,
                                       ull* __restrict__ acc) {
    const ulonglong2* wr = reinterpret_cast<const ulonglong2*>(w);
#pragma unroll
    for (int j = 0; j < NP / 4; ++j) {
        const ulonglong2 wv = wr[j];
        acc[2 * j + 0] = fma2(xv, wv.x, acc[2 * j + 0]);
        acc[2 * j + 1] = fma2(xv, wv.y, acc[2 * j + 1]);
    }
}

template <int K, int NP>
__device__ __forceinline__ void gemv2(const float* __restrict__ x,
                                      const float* __restrict__ w,
                                      ull* __restrict__ acc) {
#pragma unroll
    for (int k = 0; k < K; ++k) rowfma<NP>(pack2(x[k]), w + k * NP, acc);
}

template <int NP>
__device__ __forceinline__ void init_bias2(ull* __restrict__ acc,
                                           const float* __restrict__ b) {
    const ull* bp = reinterpret_cast<const ull*>(b);
#pragma unroll
    for (int j = 0; j < NP / 2; ++j) acc[j] = bp[j];
}

// Fused: take one finished packed pair (2 pre-activation values), lrelu both,
// fold into next-layer accumulator via 2 consecutive weight rows (w, w+NP).
template <int NP>
__device__ __forceinline__ void consume2(ull av, const float* __restrict__ w,
                                         ull* __restrict__ acc) {
    float lo, hi;
    unpack2(av, lo, hi);
    const ull plo = pack2(lrelu1(lo));
    const ull phi = pack2(lrelu1(hi));
    rowfma<NP>(plo, w, acc);
    rowfma<NP>(phi, w + NP, acc);
}

__global__ __launch_bounds__(NTHREADS, 1)
void mlp_fused_kernel(Params prm, float* __restrict__ out, int nrows) {
    extern __shared__ float sw[];

    // ---- stage all weights into SMEM (padded) ----
    load_mat(sw + OF_Wa, prm.p[3], 45, 68, 68, 45);
    load_vec(sw + OF_ba, prm.p[4], 68, 68);
    load_mat(sw + OF_Wb, prm.p[5], 102, 68, 68, 102);
    load_vec(sw + OF_bb, prm.p[6], 68, 68);
    load_mat(sw + OF_W0, prm.p[7], 140, 34, 36, 140);
    load_vec(sw + OF_B0, prm.p[8], 34, 36);
    load_mat(sw + OF_W1, prm.p[9], 34, 34, 36, 34);
    load_vec(sw + OF_B1, prm.p[10], 34, 36);
    load_mat(sw + OF_W2, prm.p[11], 34, 20, 20, 34);
    load_vec(sw + OF_B2, prm.p[12], 20, 20);
    load_mat(sw + OF_W3, prm.p[13], 20, 20, 20, 20);
    load_vec(sw + OF_B3, prm.p[14], 20, 20);
    load_mat(sw + OF_W4, prm.p[15], 20, 20, 20, 20);
    load_vec(sw + OF_B4, prm.p[16], 20, 20);
    load_mat(sw + OF_W5, prm.p[17], 20, 20, 20, 20);
    load_vec(sw + OF_B5, prm.p[18], 20, 20);
    load_mat(sw + OF_W6, prm.p[19], 20, 20, 20, 20);
    load_vec(sw + OF_B6, prm.p[20], 20, 20);
    load_mat(sw + OF_W7, prm.p[21], 20, 5, 8, 20);
    load_vec(sw + OF_B7, prm.p[22], 5, 8);
    load_mat(sw + OF_W8, prm.p[23], 5, 2, 4, 8);    // K padded 5->8
    load_vec(sw + OF_B8, prm.p[24], 2, 4);
    load_mat(sw + OF_W9, prm.p[25], 2, 1, 4, 4);    // K padded 2->4
    load_vec(sw + OF_B9, prm.p[26], 1, 4);
    __syncthreads();

    const int row = blockIdx.x * NTHREADS + threadIdx.x;
    if (row >= nrows) return;

    const float* __restrict__ A  = prm.p[0] + (long)row * 45;
    const float* __restrict__ Bi = prm.p[1] + (long)row * 102;
    const float* __restrict__ Mt = prm.p[2] + (long)row * 4;

    // layer-0 accumulator lives across both towers
    ull h0acc[18];
    init_bias2<36>(h0acc, sw + OF_B0);

    // ---- tower A: tacc = a @ Wa + ba (K chunked 3x15) ----
    ull tacc[34];
    init_bias2<68>(tacc, sw + OF_ba);
    {
        float xa[15];
#pragma unroll
        for (int c = 0; c < 3; ++c) {
#pragma unroll
            for (int k = 0; k < 15; ++k) xa[k] = A[c * 15 + k];
            gemv2<15, 68>(xa, sw + OF_Wa + c * 15 * 68, tacc);
        }
    }
    // fused lrelu + fold into layer-0 (W0 rows 0..67); tacc regs die here
#pragma unroll
    for (int j = 0; j < 34; ++j)
        consume2<36>(tacc[j], sw + OF_W0 + (2 * j) * 36, h0acc);

    // ---- tower B: tacc = b @ Wb + bb (K chunked 17x6) ----
    init_bias2<68>(tacc, sw + OF_bb);
    {
        float xb[6];
#pragma unroll
        for (int c = 0; c < 17; ++c) {
#pragma unroll
            for (int k = 0; k < 6; ++k) xb[k] = Bi[c * 6 + k];
            gemv2<6, 68>(xb, sw + OF_Wb + c * 6 * 68, tacc);
        }
    }
#pragma unroll
    for (int j = 0; j < 34; ++j)
        consume2<36>(tacc[j], sw + OF_W0 + (68 + 2 * j) * 36, h0acc);

    // ---- meta rows 136..139 of W0 (no activation on meta) ----
    {
        float xm[4];
#pragma unroll
        for (int k = 0; k < 4; ++k) xm[k] = Mt[k];
        gemv2<4, 36>(xm, sw + OF_W0 + 136 * 36, h0acc);
    }

    // ---- layer 1: 34 -> 34 (pairs 0..16 of h0acc are real; pair 17 is pad) ----
    ull accA[18];
    init_bias2<36>(accA, sw + OF_B1);
#pragma unroll
    for (int j = 0; j < 17; ++j)
        consume2<36>(h0acc[j], sw + OF_W1 + (2 * j) * 36, accA);

    // ---- layer 2: 34 -> 20 ----
    ull acc20a[10];
    init_bias2<20>(acc20a, sw + OF_B2);
#pragma unroll
    for (int j = 0; j < 17; ++j)
        consume2<20>(accA[j], sw + OF_W2 + (2 * j) * 20, acc20a);

    // ---- layers 3..6: 20 -> 20, ping-pong ----
    ull acc20b[10];
    init_bias2<20>(acc20b, sw + OF_B3);
#pragma unroll
    for (int j = 0; j < 10; ++j)
        consume2<20>(acc20a[j], sw + OF_W3 + (2 * j) * 20, acc20b);

    init_bias2<20>(acc20a, sw + OF_B4);
#pragma unroll
    for (int j = 0; j < 10; ++j)
        consume2<20>(acc20b[j], sw + OF_W4 + (2 * j) * 20, acc20a);

    init_bias2<20>(acc20b, sw + OF_B5);
#pragma unroll
    for (int j = 0; j < 10; ++j)
        consume2<20>(acc20a[j], sw + OF_W5 + (2 * j) * 20, acc20b);

    init_bias2<20>(acc20a, sw + OF_B6);
#pragma unroll
    for (int j = 0; j < 10; ++j)
        consume2<20>(acc20b[j], sw + OF_W6 + (2 * j) * 20, acc20a);

    // ---- layer 7: 20 -> 5 (pad 8) ----
    ull acc8[4];
    init_bias2<8>(acc8, sw + OF_B7);
#pragma unroll
    for (int j = 0; j < 10; ++j)
        consume2<8>(acc20a[j], sw + OF_W7 + (2 * j) * 8, acc8);

    // ---- layer 8: 5 -> 2 (pad 4; W8 K-padded to 8 rows, pads consume zeros) ----
    ull acc4[2];
    init_bias2<4>(acc4, sw + OF_B8);
#pragma unroll
    for (int j = 0; j < 4; ++j)
        consume2<4>(acc8[j], sw + OF_W8 + (2 * j) * 4, acc4);

    // ---- layer 9: 2 -> 1 (pad 4; W9 K-padded to 4 rows) ----
    ull acc4b[2];
    init_bias2<4>(acc4b, sw + OF_B9);
#pragma unroll
    for (int j = 0; j < 2; ++j)
        consume2<4>(acc4[j], sw + OF_W9 + (2 * j) * 4, acc4b);

    float lo, hi;
    unpack2(acc4b[0], lo, hi);
    out[row] = lrelu1(lo);
}

extern "C" void kernel_launch(void* const* d_in, const int* in_sizes, int n_in,
                              void* d_out, int out_size) {
    Params prm;
    for (int i = 0; i < 27; ++i) prm.p[i] = (const float*)d_in[i];
    const int nrows = in_sizes[0] / 45;

    cudaFuncSetAttribute(mlp_fused_kernel,
                         cudaFuncAttributeMaxDynamicSharedMemorySize,
                         SMEM_BYTES);

    const int grid = (nrows + NTHREADS - 1) / NTHREADS;
    mlp_fused_kernel<<<grid, NTHREADS, SMEM_BYTES>>>(prm, (float*)d_out, nrows);
}